// round 6
// baseline (speedup 1.0000x reference)
#include <cuda_runtime.h>
#include <math.h>

#define TT 1500
#define BB 16
#define DD 512
#define HH 1024
#define KEEPF 0.8f
#define EPSF 1e-5f
#define NTOT (TT*BB*HH)
#define GRID_SCAN 128
#define REDS 65                     // padded red row stride (u64)
#define FPAD 32                     // ints per flag slot (128B)

typedef unsigned long long u64;

#define FMA2(d,a,b,c) asm("fma.rn.f32x2 %0, %1, %2, %3;" : "=l"(d) : "l"(a), "l"(b), "l"(c))
#define ADD2(d,a,b)   asm("add.rn.f32x2 %0, %1, %2;" : "=l"(d) : "l"(a), "l"(b))
#define PACK2(d,lo,hi) asm("mov.b64 %0, {%1, %2};" : "=l"(d) : "f"(lo), "f"(hi))
#define UNPACK2(lo,hi,in) asm("mov.b64 {%0, %1}, %2;" : "=f"(lo), "=f"(hi) : "l"(in))

// -------- scratch (device globals: no allocation allowed) --------
__device__ float g_wh[NTOT];
__device__ float g_wz[NTOT];
__device__ float g_h0[NTOT];
__device__ float g_hT[4*BB*HH];        // double-buffered h, 2 per layer
__device__ int   g_flags[2*GRID_SCAN*FPAD];

// =================================================================
__global__ void init_kernel(const int* __restrict__ x_len,
                            float* __restrict__ out, int out_size)
{
    int i = blockIdx.x * blockDim.x + threadIdx.x;
    if (i < 2*GRID_SCAN*FPAD) g_flags[i] = 0;
    if (i < BB*HH) {                      // zero the t=0 source buffers
        g_hT[i] = 0.f;                    // layer-0 buffer A
        g_hT[2*BB*HH + i] = 0.f;          // layer-1 buffer A
    }
    if (out_size >= NTOT + BB && i < BB) out[NTOT + i] = (float)x_len[i];
}

// =================================================================
// fused GEMM + eval BatchNorm, fp32x2-packed, DOUBLE-BUFFERED smem
// (one __syncthreads per k-tile).
// =================================================================
__global__ void __launch_bounds__(256) gemm_bn_kernel(
    const float* __restrict__ A, const float* __restrict__ W,
    float* __restrict__ C,
    const float* __restrict__ gam, const float* __restrict__ bet,
    const float* __restrict__ mu,  const float* __restrict__ var,
    int K)
{
    __shared__ float Asd[2][8][132];   // [buf][k][2m] duplicated
    __shared__ float Bs[2][8][132];    // [buf][k][n]

    int tid = threadIdx.x;
    int m0 = blockIdx.y * 64;
    int n0 = blockIdx.x * 128;

    int arow = tid >> 2;
    int acol = (tid & 3) * 2;
    int brow = tid >> 1;
    int bcol = (tid & 1) * 4;

    const float* Ap = A + (size_t)(m0 + arow) * K + acol;
    const float* Wp = W + (size_t)(n0 + brow) * K + bcol;

    float2 ar = *(const float2*)Ap;
    float4 br = *(const float4*)Wp;

    u64 acc[4][4];
    #pragma unroll
    for (int i = 0; i < 4; i++)
        #pragma unroll
        for (int j = 0; j < 4; j++) acc[i][j] = 0ull;

    int tx = tid & 15, ty = tid >> 4;
    int am2 = ty * 8;
    int bn  = tx * 8;
    int nk = K >> 3;

    for (int kt = 0; kt < nk; kt++) {
        int p = kt & 1;
        Asd[p][acol  ][2*arow] = ar.x;  Asd[p][acol  ][2*arow+1] = ar.x;
        Asd[p][acol+1][2*arow] = ar.y;  Asd[p][acol+1][2*arow+1] = ar.y;
        Bs[p][bcol  ][brow] = br.x;
        Bs[p][bcol+1][brow] = br.y;
        Bs[p][bcol+2][brow] = br.z;
        Bs[p][bcol+3][brow] = br.w;
        if (kt + 1 < nk) {
            ar = *(const float2*)(Ap + (size_t)(kt+1)*8);
            br = *(const float4*)(Wp + (size_t)(kt+1)*8);
        }
        __syncthreads();
        #pragma unroll
        for (int kk = 0; kk < 8; kk++) {
            ulonglong2 a01 = *(const ulonglong2*)&Asd[p][kk][am2];
            ulonglong2 a23 = *(const ulonglong2*)&Asd[p][kk][am2+4];
            ulonglong2 b01 = *(const ulonglong2*)&Bs[p][kk][bn];
            ulonglong2 b23 = *(const ulonglong2*)&Bs[p][kk][bn+4];
            u64 av[4] = {a01.x, a01.y, a23.x, a23.y};
            u64 bv[4] = {b01.x, b01.y, b23.x, b23.y};
            #pragma unroll
            for (int i = 0; i < 4; i++)
                #pragma unroll
                for (int j = 0; j < 4; j++)
                    FMA2(acc[i][j], av[i], bv[j], acc[i][j]);
        }
    }

    float sc[8], sh[8];
    #pragma unroll
    for (int j = 0; j < 8; j++) {
        int n = n0 + bn + j;
        float inv = rsqrtf(var[n] + EPSF);
        sc[j] = gam[n] * inv;
        sh[j] = bet[n] - mu[n] * sc[j];
    }
    u64 sc2[4], sh2[4];
    #pragma unroll
    for (int j = 0; j < 4; j++) {
        PACK2(sc2[j], sc[2*j], sc[2*j+1]);
        PACK2(sh2[j], sh[2*j], sh[2*j+1]);
    }
    #pragma unroll
    for (int i = 0; i < 4; i++) {
        size_t row = (size_t)(m0 + ty*4 + i) * HH + n0 + bn;
        u64 o[4];
        #pragma unroll
        for (int j = 0; j < 4; j++) FMA2(o[j], acc[i][j], sc2[j], sh2[j]);
        ulonglong2 s0; s0.x = o[0]; s0.y = o[1];
        ulonglong2 s1; s1.x = o[2]; s1.y = o[3];
        *(ulonglong2*)(C + row)     = s0;
        *(ulonglong2*)(C + row + 4) = s1;
    }
}

// =================================================================
// persistent liGRU scan v4: double-buffered global h exchange.
// Step head stages cur (h_{t-1}) global->smem with __ldcg (no L1
// staleness); compute from smem (U register-stationary, FFMA2);
// k-partials -> red; 4-warp reduce + shfl partner exchange; gate
// writes Hout + nxt; flag barrier.  No trailing reload phase.
// =================================================================
__global__ void __launch_bounds__(256, 1) scan_kernel(
    const float* __restrict__ WH, const float* __restrict__ WZ,
    const float* __restrict__ Uh, const float* __restrict__ Uz,
    float* __restrict__ Hout,
    float* __restrict__ hTa, float* __restrict__ hTb,
    int* __restrict__ flags)
{
    extern __shared__ float smem[];
    float* hs  = smem;                       // [16][1024]
    u64*   red = (u64*)(smem + BB*HH);       // [128][REDS]

    int tid = threadIdx.x;
    int qd  = tid >> 7;            // 0..1 quad
    int bh  = (tid >> 6) & 1;      // 0..1 batch-half
    int kg  = tid & 63;            // 0..63 k-slice
    int j0  = blockIdx.x * 8;

    // ---- stationary U in registers: pair-packed ----
    u64 uz[2][16], uh[2][16];
    #pragma unroll
    for (int pr = 0; pr < 2; pr++) {
        const float* z0 = Uz + (size_t)(j0 + qd*4 + 2*pr)*HH;
        const float* z1 = z0 + HH;
        const float* a0 = Uh + (size_t)(j0 + qd*4 + 2*pr)*HH;
        const float* a1 = a0 + HH;
        #pragma unroll
        for (int kk = 0; kk < 16; kk++) {
            int k = kg + (kk << 6);
            PACK2(uz[pr][kk], z0[k], z1[k]);
            PACK2(uh[pr][kk], a0[k], a1[k]);
        }
    }

    int r_b   = tid & 15;
    int r_grp = tid >> 4;
    int r_m   = r_grp & 1;
    int g_qd  = (r_grp >> 2) & 1;
    int g_pr  = (r_grp >> 1) & 1;
    int jg    = j0 + g_qd*4 + g_pr*2;
    bool is_red  = (tid < 128);
    bool is_gate = is_red && (r_m == 0);

    for (int t = 0; t < TT; t++) {
        const float* cur = (t & 1) ? hTb : hTa;
        float*       nxt = (t & 1) ? hTa : hTb;

        // prefetch pre-projections first (DRAM latency overlaps stage)
        float2 wz2 = make_float2(0.f, 0.f), wh2 = wz2;
        size_t ob = 0;
        if (is_gate) {
            ob = ((size_t)t*BB + r_b)*HH + jg;
            wz2 = *(const float2*)(WZ + ob);
            wh2 = *(const float2*)(WH + ob);
        }

        // ---- stage h_{t-1}: global cur -> smem hs (L1 bypass) ----
        {
            const float4* src = (const float4*)cur;
            float4* dst = (float4*)hs;
            #pragma unroll
            for (int i = 0; i < 16; i++) {
                int idx = tid + (i << 8);
                dst[idx] = __ldcg(src + idx);
            }
        }
        __syncthreads();

        // ---- compute: 4 cols x 8 b x 16 k per thread ----
        u64 az[2][8], ah[2][8];
        #pragma unroll
        for (int pr = 0; pr < 2; pr++)
            #pragma unroll
            for (int b = 0; b < 8; b++) { az[pr][b] = 0ull; ah[pr][b] = 0ull; }

        {
            const float* hb = hs + (bh << 3)*HH + kg;
            #pragma unroll
            for (int kk = 0; kk < 16; kk++) {
                const float* hk = hb + (kk << 6);
                #pragma unroll
                for (int b = 0; b < 8; b++) {
                    float hv = hk[b*HH];
                    u64 hd; PACK2(hd, hv, hv);
                    FMA2(az[0][b], hd, uz[0][kk], az[0][b]);
                    FMA2(ah[0][b], hd, uh[0][kk], ah[0][b]);
                    FMA2(az[1][b], hd, uz[1][kk], az[1][b]);
                    FMA2(ah[1][b], hd, uh[1][kk], ah[1][b]);
                }
            }
        }

        // ---- k-partial write: red[grp*16 + b][kg] ----
        {
            u64* rp = red + kg;
            #pragma unroll
            for (int pr = 0; pr < 2; pr++)
                #pragma unroll
                for (int b = 0; b < 8; b++) {
                    int bb = (bh << 3) + b;
                    rp[((qd*4 + pr*2    )*16 + bb)*REDS] = az[pr][b];
                    rp[((qd*4 + pr*2 + 1)*16 + bb)*REDS] = ah[pr][b];
                }
        }
        __syncthreads();

        // ---- 4-warp reduce + partner exchange + gate ----
        if (is_red) {
            const u64* rr = red + (size_t)tid*REDS;
            u64 s0 = 0ull, s1 = 0ull, s2 = 0ull, s3 = 0ull;
            #pragma unroll
            for (int i = 0; i < 64; i += 4) {
                ADD2(s0, s0, rr[i]);
                ADD2(s1, s1, rr[i+1]);
                ADD2(s2, s2, rr[i+2]);
                ADD2(s3, s3, rr[i+3]);
            }
            ADD2(s0, s0, s1);
            ADD2(s2, s2, s3);
            ADD2(s0, s0, s2);
            u64 part = __shfl_xor_sync(0xffffffffu, s0, 16);
            if (is_gate) {
                float z0, z1, a0, a1;
                UNPACK2(z0, z1, s0);
                UNPACK2(a0, a1, part);
                float zt0 = 1.f / (1.f + __expf(-(wz2.x + z0)));
                float zt1 = 1.f / (1.f + __expf(-(wz2.y + z1)));
                float hc0 = fmaxf(wh2.x + a0, 0.f) * KEEPF;
                float hc1 = fmaxf(wh2.y + a1, 0.f) * KEEPF;
                float2 ho = *(const float2*)(hs + r_b*HH + jg);
                float2 hn;
                hn.x = zt0*ho.x + (1.f - zt0)*hc0;
                hn.y = zt1*ho.y + (1.f - zt1)*hc1;
                *(float2*)(Hout + ob)         = hn;
                *(float2*)(nxt + r_b*HH + jg) = hn;
            }
        }
        __syncthreads();
        if (t == TT-1) break;

        // ---- release/acquire distributed-flag grid barrier ----
        if (tid == 0) {
            asm volatile("st.release.gpu.global.s32 [%0], %1;"
                         :: "l"(flags + blockIdx.x*FPAD), "r"(t+1) : "memory");
        }
        if (tid < GRID_SCAN) {
            const int* fp = flags + tid*FPAD;
            int v;
            do {
                asm volatile("ld.acquire.gpu.global.s32 %0, [%1];"
                             : "=r"(v) : "l"(fp) : "memory");
            } while (v <= t);
        }
        __syncthreads();
    }
}

// =================================================================
extern "C" void kernel_launch(void* const* d_in, const int* in_sizes, int n_in,
                              void* d_out, int out_size)
{
    const float* x     = (const float*)d_in[0];
    const int*   x_len = (const int*)  d_in[1];
    const float* whW0  = (const float*)d_in[2];
    const float* wzW0  = (const float*)d_in[3];
    const float* uhW0  = (const float*)d_in[4];
    const float* uzW0  = (const float*)d_in[5];
    const float* bnh_g0 = (const float*)d_in[6];
    const float* bnh_b0 = (const float*)d_in[7];
    const float* bnh_m0 = (const float*)d_in[8];
    const float* bnh_v0 = (const float*)d_in[9];
    const float* bnz_g0 = (const float*)d_in[10];
    const float* bnz_b0 = (const float*)d_in[11];
    const float* bnz_m0 = (const float*)d_in[12];
    const float* bnz_v0 = (const float*)d_in[13];
    const float* whW1  = (const float*)d_in[14];
    const float* wzW1  = (const float*)d_in[15];
    const float* uhW1  = (const float*)d_in[16];
    const float* uzW1  = (const float*)d_in[17];
    const float* bnh_g1 = (const float*)d_in[18];
    const float* bnh_b1 = (const float*)d_in[19];
    const float* bnh_m1 = (const float*)d_in[20];
    const float* bnh_v1 = (const float*)d_in[21];
    const float* bnz_g1 = (const float*)d_in[22];
    const float* bnz_b1 = (const float*)d_in[23];
    const float* bnz_m1 = (const float*)d_in[24];
    const float* bnz_v1 = (const float*)d_in[25];

    float* out = (float*)d_out;

    float *p_wh, *p_wz, *p_h0, *p_hT; int* p_fl;
    cudaGetSymbolAddress((void**)&p_wh, g_wh);
    cudaGetSymbolAddress((void**)&p_wz, g_wz);
    cudaGetSymbolAddress((void**)&p_h0, g_h0);
    cudaGetSymbolAddress((void**)&p_hT, g_hT);
    cudaGetSymbolAddress((void**)&p_fl, g_flags);

    int smem_scan = BB*HH*(int)sizeof(float) + 128*REDS*(int)sizeof(u64); // 132096
    cudaFuncSetAttribute(scan_kernel,
        cudaFuncAttributeMaxDynamicSharedMemorySize, smem_scan);

    init_kernel<<<128, 256>>>(x_len, out, out_size);

    dim3 gg(HH/128, (TT*BB)/64);   // (8, 375)

    // ---- layer 0 ----
    gemm_bn_kernel<<<gg, 256>>>(x, whW0, p_wh, bnh_g0, bnh_b0, bnh_m0, bnh_v0, DD);
    gemm_bn_kernel<<<gg, 256>>>(x, wzW0, p_wz, bnz_g0, bnz_b0, bnz_m0, bnz_v0, DD);
    scan_kernel<<<GRID_SCAN, 256, smem_scan>>>(p_wh, p_wz, uhW0, uzW0, p_h0,
                                               p_hT, p_hT + BB*HH, p_fl);

    // ---- layer 1 ----
    gemm_bn_kernel<<<gg, 256>>>(p_h0, whW1, p_wh, bnh_g1, bnh_b1, bnh_m1, bnh_v1, HH);
    gemm_bn_kernel<<<gg, 256>>>(p_h0, wzW1, p_wz, bnz_g1, bnz_b1, bnz_m1, bnz_v1, HH);
    scan_kernel<<<GRID_SCAN, 256, smem_scan>>>(p_wh, p_wz, uhW1, uzW1, out,
                                               p_hT + 2*BB*HH, p_hT + 3*BB*HH,
                                               p_fl + GRID_SCAN*FPAD);
}